// round 1
// baseline (speedup 1.0000x reference)
#include <cuda_runtime.h>
#include <cuda_bf16.h>

#define N_ROWS 16384
#define N_COLS 4096
#define MARGIN 0.1f

// Per-row partial sums (scratch; __device__ global so no allocation).
__device__ float g_partial[N_ROWS];

// One block = one row. 256 threads * 16 elems = 4096 columns.
__global__ void __launch_bounds__(256) mm_row_kernel(
    const float* __restrict__ cossim,
    const int* __restrict__ target)
{
    const int row = blockIdx.x;
    const float4* __restrict__ crow =
        reinterpret_cast<const float4*>(cossim + (size_t)row * N_COLS);
    const int4* __restrict__ trow =
        reinterpret_cast<const int4*>(target + (size_t)row * N_COLS);

    const int t = threadIdx.x;

    __shared__ float s_corr;
    __shared__ float s_warp[8];

    // Load 4 float4 (cossim) + 4 int4 (target) per thread; keep cossim in regs.
    float4 c[4];
    float corr_local = 0.0f;
    bool found = false;

#pragma unroll
    for (int k = 0; k < 4; k++) {
        const int idx = k * 256 + t;        // float4-granule index 0..1023
        c[k] = crow[idx];
        int4 tv = trow[idx];
        if (tv.x == 1) { corr_local = c[k].x; found = true; }
        if (tv.y == 1) { corr_local = c[k].y; found = true; }
        if (tv.z == 1) { corr_local = c[k].z; found = true; }
        if (tv.w == 1) { corr_local = c[k].w; found = true; }
    }

    // Exactly one thread in the block found the one-hot position.
    if (found) s_corr = corr_local;
    __syncthreads();
    const float corr = s_corr;

    // Hinge sum over this thread's 16 elements (correct column contributes
    // exactly MARGIN; subtracted once per row at the end).
    float sum = 0.0f;
#pragma unroll
    for (int k = 0; k < 4; k++) {
        sum += fmaxf(MARGIN + c[k].x - corr, 0.0f);
        sum += fmaxf(MARGIN + c[k].y - corr, 0.0f);
        sum += fmaxf(MARGIN + c[k].z - corr, 0.0f);
        sum += fmaxf(MARGIN + c[k].w - corr, 0.0f);
    }

    // Warp reduce
#pragma unroll
    for (int off = 16; off > 0; off >>= 1)
        sum += __shfl_down_sync(0xffffffffu, sum, off);

    const int lane = t & 31;
    const int wid  = t >> 5;
    if (lane == 0) s_warp[wid] = sum;
    __syncthreads();

    if (wid == 0) {
        float v = (lane < 8) ? s_warp[lane] : 0.0f;
#pragma unroll
        for (int off = 4; off > 0; off >>= 1)
            v += __shfl_down_sync(0xffffffffu, v, off);
        if (lane == 0)
            g_partial[row] = v - MARGIN;  // remove correct-column hinge
    }
}

// Single-block deterministic reduction of the 16384 row partials.
__global__ void __launch_bounds__(1024) mm_reduce_kernel(float* __restrict__ out)
{
    const int t = threadIdx.x;
    float s = 0.0f;
#pragma unroll
    for (int i = t; i < N_ROWS; i += 1024)
        s += g_partial[i];

#pragma unroll
    for (int off = 16; off > 0; off >>= 1)
        s += __shfl_down_sync(0xffffffffu, s, off);

    __shared__ float s_warp[32];
    const int lane = t & 31;
    const int wid  = t >> 5;
    if (lane == 0) s_warp[wid] = s;
    __syncthreads();

    if (wid == 0) {
        float v = s_warp[lane];   // exactly 32 warps
#pragma unroll
        for (int off = 16; off > 0; off >>= 1)
            v += __shfl_down_sync(0xffffffffu, v, off);
        if (lane == 0)
            out[0] = v * (1.0f / (float)N_ROWS);
    }
}

extern "C" void kernel_launch(void* const* d_in, const int* in_sizes, int n_in,
                              void* d_out, int out_size)
{
    const float* cossim = (const float*)d_in[0];
    const int*   target = (const int*)d_in[1];
    float* out = (float*)d_out;

    mm_row_kernel<<<N_ROWS, 256>>>(cossim, target);
    mm_reduce_kernel<<<1, 1024>>>(out);
}

// round 2
// speedup vs baseline: 1.0004x; 1.0004x over previous
#include <cuda_runtime.h>
#include <cuda_bf16.h>

#define N_ROWS 16384
#define N_COLS 4096
#define MARGIN 0.1f

// Per-row partial sums + completion ticket (device globals: no allocation).
__device__ float g_partial[N_ROWS];
__device__ unsigned int g_count = 0;

// One block = one row. 256 threads * 16 elems = 4096 columns.
// Last CTA to finish reduces all row partials and writes the scalar loss.
__global__ void __launch_bounds__(256) mm_fused_kernel(
    const float* __restrict__ cossim,
    const int* __restrict__ target,
    float* __restrict__ out)
{
    const int row = blockIdx.x;
    const float4* __restrict__ crow =
        reinterpret_cast<const float4*>(cossim + (size_t)row * N_COLS);
    const int4* __restrict__ trow =
        reinterpret_cast<const int4*>(target + (size_t)row * N_COLS);

    const int t = threadIdx.x;
    const int lane = t & 31;
    const int wid  = t >> 5;

    __shared__ float s_corr;
    __shared__ float s_warp[8];
    __shared__ unsigned int s_ticket;

    // ---- Front-batched wide loads (max MLP): 4x float4 + 4x int4 ----
    float4 c[4];
    int4   tv[4];
#pragma unroll
    for (int k = 0; k < 4; k++) c[k]  = crow[k * 256 + t];
#pragma unroll
    for (int k = 0; k < 4; k++) tv[k] = trow[k * 256 + t];

    // Find the one-hot column's cossim value (exactly one thread matches).
    float corr_local = 0.0f;
    bool found = false;
#pragma unroll
    for (int k = 0; k < 4; k++) {
        if (tv[k].x == 1) { corr_local = c[k].x; found = true; }
        if (tv[k].y == 1) { corr_local = c[k].y; found = true; }
        if (tv[k].z == 1) { corr_local = c[k].z; found = true; }
        if (tv[k].w == 1) { corr_local = c[k].w; found = true; }
    }
    if (found) s_corr = corr_local;
    __syncthreads();
    const float corr = s_corr;

    // Hinge sum (correct column contributes exactly MARGIN; removed once below).
    float sum = 0.0f;
#pragma unroll
    for (int k = 0; k < 4; k++) {
        sum += fmaxf(MARGIN + c[k].x - corr, 0.0f);
        sum += fmaxf(MARGIN + c[k].y - corr, 0.0f);
        sum += fmaxf(MARGIN + c[k].z - corr, 0.0f);
        sum += fmaxf(MARGIN + c[k].w - corr, 0.0f);
    }

    // Block reduce (8 warps).
#pragma unroll
    for (int off = 16; off > 0; off >>= 1)
        sum += __shfl_down_sync(0xffffffffu, sum, off);
    if (lane == 0) s_warp[wid] = sum;
    __syncthreads();

    if (t == 0) {
        float v = s_warp[0];
#pragma unroll
        for (int w = 1; w < 8; w++) v += s_warp[w];
        g_partial[row] = v - MARGIN;           // remove correct-column hinge
        __threadfence();                        // publish before ticket
        s_ticket = atomicAdd(&g_count, 1u);
    }
    __syncthreads();

    // ---- Last CTA performs the final deterministic reduction ----
    if (s_ticket == (unsigned int)(N_ROWS - 1)) {
        __threadfence();  // acquire: see all g_partial writes

        const float4* __restrict__ p4 = reinterpret_cast<const float4*>(g_partial);
        float s = 0.0f;
#pragma unroll
        for (int k = 0; k < 16; k++) {
            // 4096 float4 granules / 256 threads = 16 each; L2-resident.
            float4 v = __ldcg(&p4[k * 256 + t]);
            s += v.x + v.y + v.z + v.w;
        }

#pragma unroll
        for (int off = 16; off > 0; off >>= 1)
            s += __shfl_down_sync(0xffffffffu, s, off);
        if (lane == 0) s_warp[wid] = s;
        __syncthreads();

        if (t == 0) {
            float v = s_warp[0];
#pragma unroll
            for (int w = 1; w < 8; w++) v += s_warp[w];
            out[0] = v * (1.0f / (float)N_ROWS);
            g_count = 0;                        // reset for next graph replay
        }
    }
}

extern "C" void kernel_launch(void* const* d_in, const int* in_sizes, int n_in,
                              void* d_out, int out_size)
{
    const float* cossim = (const float*)d_in[0];
    const int*   target = (const int*)d_in[1];
    float* out = (float*)d_out;

    mm_fused_kernel<<<N_ROWS, 256>>>(cossim, target, out);
}